// round 14
// baseline (speedup 1.0000x reference)
#include <cuda_runtime.h>
#include <math.h>

// SE block: B=32, H=W=56 (HW=3136), C=256, R=16, fp32 NHWC.
// out = in * sigmoid(relu(mean_hw(in) @ W1 + b1) @ W2 + b2)
//
// R13: 3 launches, 2 groups x 16 batches (51.4 MB/group -> comfortably
// L2-resident so scale reads hit ~90%+, vs 55% with the full 103 MB set):
//   pool_excite(g0) -> [scale(g0) || pool_excite(g1)] -> scale(g1)
// Excite is folded into pool via last-block election (R11, proven ~free).
// No intra-kernel barriers (R12's straggler-spin regression reverted);
// launch boundaries provide all ordering. Output stores use st.cs so the
// write stream doesn't evict the resident group.

#define Bb      32
#define G       16            // batches per group
#define HW      3136
#define Cc      256
#define CR      16
#define CQ      64            // C/4 float4 quads per position
#define KS      98            // pool chunks per batch
#define CHUNK   32            // 3136 / 98, exact
#define SSTR    (98 * 256)    // scale stride in quads; % 64 == 0

__device__ float g_partial[Bb * KS * Cc];   // 3.2 MB scratch
__device__ float g_exc[Bb * Cc];            // 32 KB excitation
__device__ int   g_count[Bb];               // zero at load; reset by finisher

__device__ __forceinline__ void stg_cs(float4* p, float4 v) {
    asm volatile("st.global.cs.v4.f32 [%0], {%1,%2,%3,%4};"
                 :: "l"(p), "f"(v.x), "f"(v.y), "f"(v.z), "f"(v.w) : "memory");
}

// ---- pool body: batch b, chunk k (32 positions), 256 threads --------------
__device__ __forceinline__ void pool_body(const float* __restrict__ in, int b, int k)
{
    const int tid = threadIdx.x;
    const int q   = tid & 63;
    const int pg  = tid >> 6;

    const float4* __restrict__ in4 = reinterpret_cast<const float4*>(in)
                                     + (size_t)b * HW * CQ
                                     + (size_t)(k * CHUNK + pg) * CQ + q;

    float4 a0 = make_float4(0.f, 0.f, 0.f, 0.f);
    float4 a1 = a0;
    #pragma unroll
    for (int t = 0; t < CHUNK / 4; t += 2) {          // 8 loads, 2 in flight
        float4 v0 = __ldg(in4 + (size_t)(4 * t)     * CQ);
        float4 v1 = __ldg(in4 + (size_t)(4 * t + 4) * CQ);
        a0.x += v0.x; a0.y += v0.y; a0.z += v0.z; a0.w += v0.w;
        a1.x += v1.x; a1.y += v1.y; a1.z += v1.z; a1.w += v1.w;
    }
    a0.x += a1.x; a0.y += a1.y; a0.z += a1.z; a0.w += a1.w;

    __shared__ float4 s4[256];
    s4[tid] = a0;
    __syncthreads();

    if (tid < 64) {
        float4 a = s4[tid];
        float4 c = s4[tid + 64];
        float4 d = s4[tid + 128];
        float4 e = s4[tid + 192];
        float4 r = make_float4(a.x + c.x + d.x + e.x,
                               a.y + c.y + d.y + e.y,
                               a.z + c.z + d.z + e.z,
                               a.w + c.w + d.w + e.w);
        reinterpret_cast<float4*>(g_partial)[(b * KS + k) * CQ + tid] = r;
    }
    __syncthreads();
}

// ---- election + excite for batch b (after pool_body) ----------------------
__device__ __forceinline__ void excite_if_last(const float* __restrict__ W1,
                                               const float* __restrict__ b1,
                                               const float* __restrict__ W2,
                                               const float* __restrict__ b2,
                                               int b)
{
    const int tid = threadIdx.x;

    __shared__ int sLast;
    if (tid == 0) {
        __threadfence();                               // partials visible
        int ticket = atomicAdd(&g_count[b], 1);
        sLast = (ticket == KS - 1);
        if (sLast) g_count[b] = 0;                     // reset for next replay
    }
    __syncthreads();
    if (!sLast) return;
    __threadfence();

    __shared__ float sq[Cc];
    __shared__ float pj[16][CR + 1];
    __shared__ float hs[CR];

    {
        const float* __restrict__ part = g_partial + (size_t)b * KS * Cc + tid;
        float sum = 0.f;
        #pragma unroll 7
        for (int kk = 0; kk < KS; kk++)
            sum += part[kk * Cc];
        sq[tid] = sum * (1.0f / (float)HW);
    }
    __syncthreads();

    {
        const int j = tid & 15;
        const int g = tid >> 4;
        float h = 0.f;
        #pragma unroll
        for (int i2 = 0; i2 < 16; i2++)
            h = fmaf(sq[g * 16 + i2], __ldg(&W1[(g * 16 + i2) * CR + j]), h);
        pj[g][j] = h;
    }
    __syncthreads();
    if (tid < CR) {
        float h = __ldg(&b1[tid]);
        #pragma unroll
        for (int g2 = 0; g2 < 16; g2++)
            h += pj[g2][tid];
        hs[tid] = fmaxf(h, 0.f);
    }
    __syncthreads();

    float e = __ldg(&b2[tid]);
    #pragma unroll
    for (int j = 0; j < CR; j++)
        e = fmaf(hs[j], __ldg(&W2[j * Cc + tid]), e);
    g_exc[b * Cc + tid] = 1.0f / (1.0f + __expf(-e));
}

// ---- scale body: batch b, chunk sx (8 strided quads/thread) ---------------
__device__ __forceinline__ void scale_body(const float* __restrict__ in,
                                           float* __restrict__ out, int b, int sx)
{
    const int i0 = sx * 256 + threadIdx.x;

    const float4* __restrict__ in4  = reinterpret_cast<const float4*>(in)
                                      + (size_t)b * HW * CQ;
    float4* __restrict__       out4 = reinterpret_cast<float4*>(out)
                                      + (size_t)b * HW * CQ;

    const float4 e = *(reinterpret_cast<const float4*>(g_exc)
                       + b * CQ + (threadIdx.x & 63));

    float4 v[8];
    #pragma unroll
    for (int m = 0; m < 8; m++)
        v[m] = __ldg(in4 + i0 + m * SSTR);

    #pragma unroll
    for (int m = 0; m < 8; m++) {
        v[m].x *= e.x; v[m].y *= e.y; v[m].z *= e.z; v[m].w *= e.w;
        stg_cs(out4 + i0 + m * SSTR, v[m]);
    }
}

// ---------------------------------------------------------------------------
// Launch 1: pool + excite for group g0. grid (KS, G).
__global__ void __launch_bounds__(256) se_pool_excite(const float* __restrict__ in,
                                                      const float* __restrict__ W1,
                                                      const float* __restrict__ b1,
                                                      const float* __restrict__ W2,
                                                      const float* __restrict__ b2,
                                                      int bbase)
{
    const int b = bbase + blockIdx.y;
    pool_body(in, b, blockIdx.x);
    excite_if_last(W1, b1, W2, b2, b);
}

// Launch 2: even x -> scale g0 chunk x/2 (reversed), odd x -> pool+excite g1.
__global__ void __launch_bounds__(256) se_scale_pool(const float* __restrict__ in,
                                                     float* __restrict__ out,
                                                     const float* __restrict__ W1,
                                                     const float* __restrict__ b1,
                                                     const float* __restrict__ W2,
                                                     const float* __restrict__ b2,
                                                     int sbase, int pbase)
{
    const int chunk = blockIdx.x >> 1;
    if ((blockIdx.x & 1) == 0) {
        scale_body(in, out, sbase + (G - 1 - blockIdx.y), (KS - 1) - chunk);
    } else {
        const int b = pbase + blockIdx.y;
        pool_body(in, b, chunk);
        excite_if_last(W1, b1, W2, b2, b);
    }
}

// Launch 3: scale group g1 (reversed traversal).
__global__ void __launch_bounds__(256) se_scale(const float* __restrict__ in,
                                                float* __restrict__ out, int bbase)
{
    scale_body(in, out, bbase + (G - 1 - blockIdx.y), (KS - 1) - blockIdx.x);
}

// ---------------------------------------------------------------------------
extern "C" void kernel_launch(void* const* d_in, const int* in_sizes, int n_in,
                              void* d_out, int out_size)
{
    const float* in = (const float*)d_in[0];
    const float* W1 = (const float*)d_in[1];
    const float* b1 = (const float*)d_in[2];
    const float* W2 = (const float*)d_in[3];
    const float* b2 = (const float*)d_in[4];
    float* out = (float*)d_out;

    se_pool_excite<<<dim3(KS, G), 256>>>(in, W1, b1, W2, b2, 0);          // 1568
    se_scale_pool <<<dim3(2 * KS, G), 256>>>(in, out, W1, b1, W2, b2, 0, G); // 3136
    se_scale      <<<dim3(KS, G), 256>>>(in, out, G);                     // 1568
}

// round 15
// speedup vs baseline: 1.2300x; 1.2300x over previous
#include <cuda_runtime.h>
#include <math.h>

// SE block: B=32, H=W=56 (HW=3136), C=256, R=16, fp32 NHWC.
// out = in * sigmoid(relu(mean_hw(in) @ W1 + b1) @ W2 + b2)
//
// R14 = R11 skeleton (2 launches, election-excite folded into pool) +
//  (a) pool reads input with createpolicy evict_last + ld.L2::cache_hint
//      (policy-register form keeps 128-bit loads, unlike the v8-only direct
//      modifier that regressed in R4) -> input stays L2-resident for scale;
//  (b) scale reads with evict_first policy, writes st.cs, and runs as
//      EXACTLY one wave: grid (37,32)=1184 blocks, 21 quads/thread + tail.

#define Bb      32
#define HW      3136
#define Cc      256
#define CR      16
#define KSPLIT  37            // 32*37 = 1184 blocks = 8/SM on 148 SMs
#define CHUNKP  85            // ceil(3136/37); last chunk is 76
#define CQ      64            // C/4 float4 quads per position
#define SWARPQ  9472          // scale stride: 37 blocks * 256 threads; %64==0
#define SFULL   21            // full iterations: 21*9472 = 198912
#define STAIL   1792          // 200704 - 198912

__device__ float g_partial[Bb * KSPLIT * Cc];   // ~1.2 MB scratch
__device__ float g_exc[Bb * Cc];                // 32 KB excitation
__device__ int   g_count[Bb];                   // zero at load; reset by finisher

// ---- policy-register cache hints ------------------------------------------
__device__ __forceinline__ unsigned long long mk_policy_evict_last() {
    unsigned long long pol;
    asm volatile("createpolicy.fractional.L2::evict_last.b64 %0, 1.0;" : "=l"(pol));
    return pol;
}
__device__ __forceinline__ unsigned long long mk_policy_evict_first() {
    unsigned long long pol;
    asm volatile("createpolicy.fractional.L2::evict_first.b64 %0, 1.0;" : "=l"(pol));
    return pol;
}
__device__ __forceinline__ float4 ldg_pol(const float4* p, unsigned long long pol) {
    float4 v;
    asm volatile("ld.global.nc.L2::cache_hint.v4.f32 {%0,%1,%2,%3}, [%4], %5;"
                 : "=f"(v.x), "=f"(v.y), "=f"(v.z), "=f"(v.w)
                 : "l"(p), "l"(pol));
    return v;
}
__device__ __forceinline__ void stg_cs(float4* p, float4 v) {
    asm volatile("st.global.cs.v4.f32 [%0], {%1,%2,%3,%4};"
                 :: "l"(p), "f"(v.x), "f"(v.y), "f"(v.z), "f"(v.w) : "memory");
}

// ---------------------------------------------------------------------------
// Launch 1: pool partials (evict_last-pinned reads) + last-block excite.
// grid (KSPLIT, Bb) x 256.  R11-proven body.
// ---------------------------------------------------------------------------
__global__ void __launch_bounds__(256) se_pool_excite(const float* __restrict__ in,
                                                      const float* __restrict__ W1,
                                                      const float* __restrict__ b1,
                                                      const float* __restrict__ W2,
                                                      const float* __restrict__ b2)
{
    const int k   = blockIdx.x;
    const int b   = blockIdx.y;
    const int tid = threadIdx.x;
    const int q   = tid & 63;
    const int pg  = tid >> 6;

    const unsigned long long pol = mk_policy_evict_last();

    const float4* __restrict__ in4 = reinterpret_cast<const float4*>(in)
                                     + (size_t)b * HW * CQ;

    float4 a0 = make_float4(0.f, 0.f, 0.f, 0.f);
    float4 a1 = make_float4(0.f, 0.f, 0.f, 0.f);
    const int pBeg = k * CHUNKP;
    const int pEnd = (pBeg + CHUNKP < HW) ? (pBeg + CHUNKP) : HW;
    int p = pBeg + pg;
    for (; p + 4 < pEnd; p += 8) {
        float4 v0 = ldg_pol(&in4[(size_t)p * CQ + q], pol);
        float4 v1 = ldg_pol(&in4[(size_t)(p + 4) * CQ + q], pol);
        a0.x += v0.x; a0.y += v0.y; a0.z += v0.z; a0.w += v0.w;
        a1.x += v1.x; a1.y += v1.y; a1.z += v1.z; a1.w += v1.w;
    }
    if (p < pEnd) {
        float4 v0 = ldg_pol(&in4[(size_t)p * CQ + q], pol);
        a0.x += v0.x; a0.y += v0.y; a0.z += v0.z; a0.w += v0.w;
    }
    a0.x += a1.x; a0.y += a1.y; a0.z += a1.z; a0.w += a1.w;

    __shared__ float4 s4[256];
    s4[tid] = a0;
    __syncthreads();

    if (tid < 64) {
        float4 a = s4[tid];
        float4 c = s4[tid + 64];
        float4 d = s4[tid + 128];
        float4 e = s4[tid + 192];
        float4 r = make_float4(a.x + c.x + d.x + e.x,
                               a.y + c.y + d.y + e.y,
                               a.z + c.z + d.z + e.z,
                               a.w + c.w + d.w + e.w);
        reinterpret_cast<float4*>(g_partial)[(b * KSPLIT + k) * CQ + tid] = r;
    }
    __syncthreads();

    // ---- last-block election for this batch --------------------------------
    __shared__ int sLast;
    if (tid == 0) {
        __threadfence();
        int ticket = atomicAdd(&g_count[b], 1);
        sLast = (ticket == KSPLIT - 1);
        if (sLast) g_count[b] = 0;                     // reset for next replay
    }
    __syncthreads();
    if (!sLast) return;
    __threadfence();

    // ---- excite for batch b (256 threads, partials L2-hot) -----------------
    __shared__ float sq[Cc];
    __shared__ float pj[16][CR + 1];
    __shared__ float hs[CR];

    {
        const float* __restrict__ part = g_partial + (size_t)b * KSPLIT * Cc + tid;
        float sum = 0.f;
        #pragma unroll
        for (int kk = 0; kk < KSPLIT; kk++)
            sum += part[kk * Cc];
        sq[tid] = sum * (1.0f / (float)HW);
    }
    __syncthreads();

    {
        const int j = tid & 15;
        const int g = tid >> 4;
        float h = 0.f;
        #pragma unroll
        for (int i2 = 0; i2 < 16; i2++)
            h = fmaf(sq[g * 16 + i2], __ldg(&W1[(g * 16 + i2) * CR + j]), h);
        pj[g][j] = h;
    }
    __syncthreads();
    if (tid < CR) {
        float h = __ldg(&b1[tid]);
        #pragma unroll
        for (int g2 = 0; g2 < 16; g2++)
            h += pj[g2][tid];
        hs[tid] = fmaxf(h, 0.f);
    }
    __syncthreads();

    float e = __ldg(&b2[tid]);
    #pragma unroll
    for (int j = 0; j < CR; j++)
        e = fmaf(hs[j], __ldg(&W2[j * Cc + tid]), e);
    g_exc[b * Cc + tid] = 1.0f / (1.0f + __expf(-e));
}

// ---------------------------------------------------------------------------
// Launch 2: out = in * exc[b,c]. grid (37, Bb) x 256 = 1184 blocks = exactly
// one wave. Per batch: 9472 threads x 21 quads + 1792-thread tail.
// Stride 9472 % 64 == 0 -> one excitation quad per thread. Reads demoted via
// evict_first policy; writes stream past L2 via st.cs.
// ---------------------------------------------------------------------------
__global__ void __launch_bounds__(256, 8) se_scale(const float* __restrict__ in,
                                                   float* __restrict__ out)
{
    const int b   = (Bb - 1) - blockIdx.y;             // most-recent batches first
    const int idx = blockIdx.x * 256 + threadIdx.x;    // 0..9471

    const unsigned long long pol = mk_policy_evict_first();

    const float4* __restrict__ in4  = reinterpret_cast<const float4*>(in)
                                      + (size_t)b * HW * CQ;
    float4* __restrict__       out4 = reinterpret_cast<float4*>(out)
                                      + (size_t)b * HW * CQ;

    const float4 e = *(reinterpret_cast<const float4*>(g_exc)
                       + b * CQ + (threadIdx.x & 63));

    // 3 batches of 7 independent loads (21 total), then store each batch.
    #pragma unroll
    for (int g = 0; g < 3; g++) {
        float4 v[7];
        #pragma unroll
        for (int m = 0; m < 7; m++)
            v[m] = ldg_pol(in4 + idx + (size_t)(g * 7 + m) * SWARPQ, pol);
        #pragma unroll
        for (int m = 0; m < 7; m++) {
            v[m].x *= e.x; v[m].y *= e.y; v[m].z *= e.z; v[m].w *= e.w;
            stg_cs(out4 + idx + (size_t)(g * 7 + m) * SWARPQ, v[m]);
        }
    }
    if (idx < STAIL) {
        float4 v = ldg_pol(in4 + idx + (size_t)SFULL * SWARPQ, pol);
        v.x *= e.x; v.y *= e.y; v.z *= e.z; v.w *= e.w;
        stg_cs(out4 + idx + (size_t)SFULL * SWARPQ, v);
    }
}

// ---------------------------------------------------------------------------
extern "C" void kernel_launch(void* const* d_in, const int* in_sizes, int n_in,
                              void* d_out, int out_size)
{
    const float* in = (const float*)d_in[0];
    const float* W1 = (const float*)d_in[1];
    const float* b1 = (const float*)d_in[2];
    const float* W2 = (const float*)d_in[3];
    const float* b2 = (const float*)d_in[4];
    float* out = (float*)d_out;

    se_pool_excite<<<dim3(KSPLIT, Bb), 256>>>(in, W1, b1, W2, b2);  // 1184 blocks
    se_scale      <<<dim3(KSPLIT, Bb), 256>>>(in, out);             // 1184 blocks
}

// round 16
// speedup vs baseline: 1.2392x; 1.0075x over previous
#include <cuda_runtime.h>
#include <math.h>

// SE block: B=32, H=W=56 (HW=3136), C=256, R=16, fp32 NHWC.
// out = in * sigmoid(relu(mean_hw(in) @ W1 + b1) @ W2 + b2)
//
// R15 = R11 skeleton (2 launches, election-excite inside pool) with scale
// rebuilt for DRAM page locality:
//  - each scale block covers a CONTIGUOUS 32 KB span (was 8 scattered 4 KB
//    fragments at 401 KB stride) for both its read and write streams;
//  - output stores use st.global.wt (write-through: no dirty L2 lines, input
//    stays resident; .cs/.evict hints were measured no-ops for this).

#define Bb      32
#define HW      3136
#define Cc      256
#define CR      16
#define KSPLIT  37            // 32*37 = 1184 blocks = 8/SM on 148 SMs
#define CHUNKP  85            // ceil(3136/37); last chunk is 76
#define CQ      64            // C/4 float4 quads per position
#define SBLK    98            // scale blocks per batch; 98*2048 = 200704 quads

__device__ float g_partial[Bb * KSPLIT * Cc];   // ~1.2 MB scratch
__device__ float g_exc[Bb * Cc];                // 32 KB excitation
__device__ int   g_count[Bb];                   // zero at load; reset by finisher

__device__ __forceinline__ void stg_wt(float4* p, float4 v) {
    asm volatile("st.global.wt.v4.f32 [%0], {%1,%2,%3,%4};"
                 :: "l"(p), "f"(v.x), "f"(v.y), "f"(v.z), "f"(v.w) : "memory");
}

// ---------------------------------------------------------------------------
// Launch 1: pool partials + last-block excite. grid (KSPLIT, Bb) x 256.
// Byte-identical to R11's proven kernel (20.0 us, 5.37 TB/s, occ 98%).
// ---------------------------------------------------------------------------
__global__ void __launch_bounds__(256) se_pool_excite(const float* __restrict__ in,
                                                      const float* __restrict__ W1,
                                                      const float* __restrict__ b1,
                                                      const float* __restrict__ W2,
                                                      const float* __restrict__ b2)
{
    const int k   = blockIdx.x;
    const int b   = blockIdx.y;
    const int tid = threadIdx.x;
    const int q   = tid & 63;
    const int pg  = tid >> 6;

    const float4* __restrict__ in4 = reinterpret_cast<const float4*>(in)
                                     + (size_t)b * HW * CQ;

    float4 a0 = make_float4(0.f, 0.f, 0.f, 0.f);
    float4 a1 = make_float4(0.f, 0.f, 0.f, 0.f);
    const int pBeg = k * CHUNKP;
    const int pEnd = (pBeg + CHUNKP < HW) ? (pBeg + CHUNKP) : HW;
    int p = pBeg + pg;
    for (; p + 4 < pEnd; p += 8) {
        float4 v0 = __ldg(&in4[(size_t)p * CQ + q]);
        float4 v1 = __ldg(&in4[(size_t)(p + 4) * CQ + q]);
        a0.x += v0.x; a0.y += v0.y; a0.z += v0.z; a0.w += v0.w;
        a1.x += v1.x; a1.y += v1.y; a1.z += v1.z; a1.w += v1.w;
    }
    if (p < pEnd) {
        float4 v0 = __ldg(&in4[(size_t)p * CQ + q]);
        a0.x += v0.x; a0.y += v0.y; a0.z += v0.z; a0.w += v0.w;
    }
    a0.x += a1.x; a0.y += a1.y; a0.z += a1.z; a0.w += a1.w;

    __shared__ float4 s4[256];
    s4[tid] = a0;
    __syncthreads();

    if (tid < 64) {
        float4 a = s4[tid];
        float4 c = s4[tid + 64];
        float4 d = s4[tid + 128];
        float4 e = s4[tid + 192];
        float4 r = make_float4(a.x + c.x + d.x + e.x,
                               a.y + c.y + d.y + e.y,
                               a.z + c.z + d.z + e.z,
                               a.w + c.w + d.w + e.w);
        reinterpret_cast<float4*>(g_partial)[(b * KSPLIT + k) * CQ + tid] = r;
    }
    __syncthreads();

    // ---- last-block election for this batch --------------------------------
    __shared__ int sLast;
    if (tid == 0) {
        __threadfence();                               // partials visible
        int ticket = atomicAdd(&g_count[b], 1);
        sLast = (ticket == KSPLIT - 1);
        if (sLast) g_count[b] = 0;                     // reset for next replay
    }
    __syncthreads();
    if (!sLast) return;
    __threadfence();

    // ---- excite for batch b (256 threads, partials L2-hot) -----------------
    __shared__ float sq[Cc];
    __shared__ float pj[16][CR + 1];
    __shared__ float hs[CR];

    {
        const float* __restrict__ part = g_partial + (size_t)b * KSPLIT * Cc + tid;
        float sum = 0.f;
        #pragma unroll
        for (int kk = 0; kk < KSPLIT; kk++)
            sum += part[kk * Cc];
        sq[tid] = sum * (1.0f / (float)HW);
    }
    __syncthreads();

    {
        const int j = tid & 15;
        const int g = tid >> 4;
        float h = 0.f;
        #pragma unroll
        for (int i2 = 0; i2 < 16; i2++)
            h = fmaf(sq[g * 16 + i2], __ldg(&W1[(g * 16 + i2) * CR + j]), h);
        pj[g][j] = h;
    }
    __syncthreads();
    if (tid < CR) {
        float h = __ldg(&b1[tid]);
        #pragma unroll
        for (int g2 = 0; g2 < 16; g2++)
            h += pj[g2][tid];
        hs[tid] = fmaxf(h, 0.f);
    }
    __syncthreads();

    float e = __ldg(&b2[tid]);
    #pragma unroll
    for (int j = 0; j < CR; j++)
        e = fmaf(hs[j], __ldg(&W2[j * Cc + tid]), e);
    g_exc[b * Cc + tid] = 1.0f / (1.0f + __expf(-e));
}

// ---------------------------------------------------------------------------
// Launch 2: out = in * exc[b,c]. grid (SBLK, Bb) x 256. Each block covers a
// CONTIGUOUS 2048-quad (32 KB) span: thread tid handles quads
// bx*2048 + tid + m*256, m=0..7 (stride 4 KB; 256 % 64 == 0 so the per-thread
// excitation quad is invariant). 8 independent LDG.128 in flight; output via
// st.global.wt. Reversed traversal (most-recently-pooled lines first).
// ---------------------------------------------------------------------------
__global__ void __launch_bounds__(256) se_scale(const float* __restrict__ in,
                                                float* __restrict__ out)
{
    const int b  = (Bb - 1)   - blockIdx.y;
    const int bx = (SBLK - 1) - blockIdx.x;
    const size_t i0 = (size_t)bx * 2048 + threadIdx.x;

    const float4* __restrict__ in4  = reinterpret_cast<const float4*>(in)
                                      + (size_t)b * HW * CQ;
    float4* __restrict__       out4 = reinterpret_cast<float4*>(out)
                                      + (size_t)b * HW * CQ;

    const float4 e = *(reinterpret_cast<const float4*>(g_exc)
                       + b * CQ + (threadIdx.x & 63));

    float4 v[8];
    #pragma unroll
    for (int m = 0; m < 8; m++)
        v[m] = __ldg(in4 + i0 + m * 256);

    #pragma unroll
    for (int m = 0; m < 8; m++) {
        v[m].x *= e.x; v[m].y *= e.y; v[m].z *= e.z; v[m].w *= e.w;
        stg_wt(out4 + i0 + m * 256, v[m]);
    }
}

// ---------------------------------------------------------------------------
extern "C" void kernel_launch(void* const* d_in, const int* in_sizes, int n_in,
                              void* d_out, int out_size)
{
    const float* in = (const float*)d_in[0];
    const float* W1 = (const float*)d_in[1];
    const float* b1 = (const float*)d_in[2];
    const float* W2 = (const float*)d_in[3];
    const float* b2 = (const float*)d_in[4];
    float* out = (float*)d_out;

    se_pool_excite<<<dim3(KSPLIT, Bb), 256>>>(in, W1, b1, W2, b2);  // 1184 blocks
    se_scale      <<<dim3(SBLK,   Bb), 256>>>(in, out);             // 3136 blocks
}